// round 8
// baseline (speedup 1.0000x reference)
#include <cuda_runtime.h>
#include <cuda_bf16.h>
#include <cstdint>

#define T_DIM 512
#define B_DIM 16
#define D_DIM 1024
#define WIN   16
#define WSZ   33           // window taps
#define TT    32           // t-tile per block
#define DC    128          // d-chunk (floats) per block
#define HR    (TT + 2*WIN) // halo rows = 64

__device__ float g_a[T_DIM * B_DIM];
__device__ float g_c[T_DIM * B_DIM];

// ---------------------------------------------------------------------------
// Kernel A: a = x·w_cur, c = x·w_seq per (t,b) row. One warp per row.
// ---------------------------------------------------------------------------
__global__ void k_dots(const float* __restrict__ x, const float* __restrict__ w) {
    int warp = (blockIdx.x << 3) + (threadIdx.x >> 5);
    int lane = threadIdx.x & 31;
    const float4* xr = reinterpret_cast<const float4*>(x) + (size_t)warp * 256;
    const float4* wc = reinterpret_cast<const float4*>(w);
    const float4* ws = wc + 256;

    float4 xv[8];
#pragma unroll
    for (int i = 0; i < 8; i++) xv[i] = xr[lane + i * 32];

    float sa = 0.f, sc = 0.f;
#pragma unroll
    for (int i = 0; i < 8; i++) {
        int k = lane + i * 32;
        float4 a4 = __ldg(&wc[k]);
        float4 c4 = __ldg(&ws[k]);
        sa += xv[i].x * a4.x + xv[i].y * a4.y + xv[i].z * a4.z + xv[i].w * a4.w;
        sc += xv[i].x * c4.x + xv[i].y * c4.y + xv[i].z * c4.z + xv[i].w * c4.w;
    }
#pragma unroll
    for (int off = 16; off; off >>= 1) {
        sa += __shfl_xor_sync(0xFFFFFFFFu, sa, off);
        sc += __shfl_xor_sync(0xFFFFFFFFu, sc, off);
    }
    if (lane == 0) { g_a[warp] = sa; g_c[warp] = sc; }
}

// ---------------------------------------------------------------------------
// helpers
// ---------------------------------------------------------------------------
__device__ __forceinline__ void fma2(unsigned long long& a,
                                     unsigned long long xv,
                                     unsigned long long pp) {
    asm("fma.rn.f32x2 %0, %1, %2, %0;" : "+l"(a) : "l"(xv), "l"(pp));
}
__device__ __forceinline__ float2 u2f(unsigned long long v) {
    float2 r;
    asm("mov.b64 {%0,%1}, %2;" : "=f"(r.x), "=f"(r.y) : "l"(v));
    return r;
}
__device__ __forceinline__ void cp16(void* s, const void* g) {
    unsigned sa = (unsigned)__cvta_generic_to_shared(s);
    asm volatile("cp.async.cg.shared.global [%0], [%1], 16;" :: "r"(sa), "l"(g));
}
__device__ __forceinline__ void cp_commit() {
    asm volatile("cp.async.commit_group;");
}
template <int N>
__device__ __forceinline__ void cp_wait() {
    asm volatile("cp.async.wait_group %0;" :: "n"(N));
}

// ---------------------------------------------------------------------------
// Kernel B (fused softmax + windowed sum + x-copy).
// 128 threads: d4 = tid&31 (float4 column), tg = tid>>5 (8 t's per thread).
// pd stored pre-duplicated {p,p} (16KB) -> zero repack movs in the hot loop.
// smem ~49.5KB -> 4 CTAs/SM.
// ---------------------------------------------------------------------------
__global__ void __launch_bounds__(128, 4)
k_attn(const float* __restrict__ x, const float* __restrict__ bb,
       float* __restrict__ out) {
    extern __shared__ float smem[];
    float*  xs = smem;                                       // 64*128 f = 32KB
    float2* pd = reinterpret_cast<float2*>(smem + HR * DC);  // 64*32 f2 = 16KB
    float*  sc_a = reinterpret_cast<float*>(pd + HR * TT);   // 32 f
    float*  sc_c = sc_a + TT;                                // 64 f

    const int tid = threadIdx.x;
    const int d0 = blockIdx.x * DC;
    const int t0 = blockIdx.y * TT;
    const int b  = blockIdx.z;

    // ---- issue 4 cp.async stages (16 rows x 32 f4 each = 512 f4/stage) ----
    const float4* x4 = reinterpret_cast<const float4*>(x);
    float4* xs4 = reinterpret_cast<float4*>(xs);
#pragma unroll
    for (int s = 0; s < 4; s++) {
#pragma unroll
        for (int k = 0; k < 4; k++) {
            int idx = s * 512 + k * 128 + tid;
            int row = idx >> 5;
            int col = idx & 31;
            int gr = t0 - WIN + row;
            gr = gr < 0 ? 0 : (gr > T_DIM - 1 ? T_DIM - 1 : gr);
            cp16(&xs4[idx], &x4[((size_t)gr * B_DIM + b) * (D_DIM / 4) + (d0 >> 2) + col]);
        }
        cp_commit();
    }

    // ---- preload a/c windows + zero pd while loads fly ----
    if (tid < TT) sc_a[tid] = g_a[(t0 + tid) * B_DIM + b];
    else if (tid < TT + HR) {
        int i = tid - TT;
        int gr = t0 - WIN + i;
        sc_c[i] = (gr >= 0 && gr < T_DIM) ? g_c[gr * B_DIM + b] : -INFINITY;
    }
#pragma unroll
    for (int i = tid; i < HR * TT; i += 128) pd[i] = make_float2(0.f, 0.f);
    __syncthreads();

    // ---- warp 0: softmax for 32 t's, scatter {p,p} diagonally into pd ----
    if (tid < 32) {
        const int tl = tid;
        const float base = sc_a[tl] + bb[0];
        float sv[WSZ];
        float m = -INFINITY;
#pragma unroll
        for (int wi = 0; wi < WSZ; wi++) {
            float v = base + sc_c[tl + wi];
            sv[wi] = v;
            m = fmaxf(m, v);
        }
        float sum = 0.f;
#pragma unroll
        for (int wi = 0; wi < WSZ; wi++) {
            float e = (sv[wi] == -INFINITY) ? 0.f : __expf(sv[wi] - m);
            sv[wi] = e;
            sum += e;
        }
        float inv = 1.f / sum;
#pragma unroll
        for (int wi = 0; wi < WSZ; wi++) {
            float p = sv[wi] * inv;
            pd[(tl + wi) * TT + tl] = make_float2(p, p);
        }
    }

    const int d4 = tid & 31;    // float4 column
    const int tg = tid >> 5;    // warp id = t-group (8 t's)
    const int tb = tg * 8;

    unsigned long long acc[16];
#pragma unroll
    for (int j = 0; j < 16; j++) acc[j] = 0ULL;

    const ulonglong2* xsq = reinterpret_cast<const ulonglong2*>(xs);
    const ulonglong2* pdq = reinterpret_cast<const ulonglong2*>(pd);
    float4* o4 = reinterpret_cast<float4*>(out);
    const size_t ocopy = ((size_t)(t0 + tb) * B_DIM + b) * 512 + (d0 >> 2) + d4;

#define ROW_STEP(r, DO_COPY)                                              \
    {                                                                     \
        int row = tb + (r);                                               \
        ulonglong2 xv = xsq[row * 32 + d4];                               \
        int pbase = row * 16 + tg * 4;   /* pd[row][tb..tb+7] as 4 ull2 */\
        ulonglong2 q0 = pdq[pbase + 0];                                   \
        ulonglong2 q1 = pdq[pbase + 1];                                   \
        ulonglong2 q2 = pdq[pbase + 2];                                   \
        ulonglong2 q3 = pdq[pbase + 3];                                   \
        fma2(acc[0],  xv.x, q0.x); fma2(acc[1],  xv.y, q0.x);             \
        fma2(acc[2],  xv.x, q0.y); fma2(acc[3],  xv.y, q0.y);             \
        fma2(acc[4],  xv.x, q1.x); fma2(acc[5],  xv.y, q1.x);             \
        fma2(acc[6],  xv.x, q1.y); fma2(acc[7],  xv.y, q1.y);             \
        fma2(acc[8],  xv.x, q2.x); fma2(acc[9],  xv.y, q2.x);             \
        fma2(acc[10], xv.x, q2.y); fma2(acc[11], xv.y, q2.y);             \
        fma2(acc[12], xv.x, q3.x); fma2(acc[13], xv.y, q3.x);             \
        fma2(acc[14], xv.x, q3.y); fma2(acc[15], xv.y, q3.y);             \
        if (DO_COPY) {                                                    \
            float2 lo = u2f(xv.x), hi = u2f(xv.y);                        \
            __stcs(&o4[ocopy + (size_t)((r) - 16) * B_DIM * 512],         \
                   make_float4(lo.x, lo.y, hi.x, hi.y));                  \
        }                                                                 \
    }

    // step r touches row tb+r (tb <= 24). Stage s covers rows [16s,16s+15].
    cp_wait<2>();            // rows 0..31 ready
    __syncthreads();         // + pd visible
#pragma unroll
    for (int r = 0; r < 8; r++) ROW_STEP(r, false);   // max row 31

    cp_wait<1>();            // rows 0..47 ready
    __syncthreads();
#pragma unroll
    for (int r = 8; r < 16; r++) ROW_STEP(r, false);  // max row 39
#pragma unroll
    for (int r = 16; r < 24; r++) ROW_STEP(r, true);  // copy rows, max row 47

    cp_wait<0>();            // all rows
    __syncthreads();
#pragma unroll
    for (int r = 24; r < 40; r++) ROW_STEP(r, false); // max row 63
#undef ROW_STEP

    // attn half: out[t, b, D + d]
#pragma unroll
    for (int j = 0; j < 8; j++) {
        int t = t0 + tb + j;
        float2 lo = u2f(acc[2 * j]);
        float2 hi = u2f(acc[2 * j + 1]);
        __stcs(&o4[((size_t)t * B_DIM + b) * 512 + (D_DIM / 4) + (d0 >> 2) + d4],
               make_float4(lo.x, lo.y, hi.x, hi.y));
    }
}

// ---------------------------------------------------------------------------
extern "C" void kernel_launch(void* const* d_in, const int* in_sizes, int n_in,
                              void* d_out, int out_size) {
    const float* x  = reinterpret_cast<const float*>(d_in[0]);
    const float* w  = reinterpret_cast<const float*>(d_in[1]);
    const float* bb = reinterpret_cast<const float*>(d_in[2]);
    float* out = reinterpret_cast<float*>(d_out);

    const int smem_bytes = HR * DC * 4 + HR * TT * 8 + (TT + HR) * 4 + 16;
    cudaFuncSetAttribute(k_attn, cudaFuncAttributeMaxDynamicSharedMemorySize, smem_bytes);

    k_dots<<<(T_DIM * B_DIM) / 8, 256>>>(x, w);
    dim3 grid(D_DIM / DC, T_DIM / TT, B_DIM);
    k_attn<<<grid, 128, smem_bytes>>>(x, bb, out);
}

// round 9
// speedup vs baseline: 1.0375x; 1.0375x over previous
#include <cuda_runtime.h>
#include <cuda_bf16.h>
#include <cstdint>

#define T_DIM 512
#define B_DIM 16
#define D_DIM 1024
#define WIN   16
#define WSZ   33           // window taps
#define TT    32           // t-tile per block
#define DC    128          // d-chunk (floats) per block
#define HR    (TT + 2*WIN) // halo rows = 64

__device__ float g_a[T_DIM * B_DIM];
__device__ float g_c[T_DIM * B_DIM];

// ---------------------------------------------------------------------------
// Kernel A: a = x·w_cur, c = x·w_seq per (t,b) row. One warp per row.
// ---------------------------------------------------------------------------
__global__ void k_dots(const float* __restrict__ x, const float* __restrict__ w) {
    int warp = (blockIdx.x << 3) + (threadIdx.x >> 5);
    int lane = threadIdx.x & 31;
    const float4* xr = reinterpret_cast<const float4*>(x) + (size_t)warp * 256;
    const float4* wc = reinterpret_cast<const float4*>(w);
    const float4* ws = wc + 256;

    float4 xv[8];
#pragma unroll
    for (int i = 0; i < 8; i++) xv[i] = xr[lane + i * 32];

    float sa = 0.f, sc = 0.f;
#pragma unroll
    for (int i = 0; i < 8; i++) {
        int k = lane + i * 32;
        float4 a4 = __ldg(&wc[k]);
        float4 c4 = __ldg(&ws[k]);
        sa += xv[i].x * a4.x + xv[i].y * a4.y + xv[i].z * a4.z + xv[i].w * a4.w;
        sc += xv[i].x * c4.x + xv[i].y * c4.y + xv[i].z * c4.z + xv[i].w * c4.w;
    }
#pragma unroll
    for (int off = 16; off; off >>= 1) {
        sa += __shfl_xor_sync(0xFFFFFFFFu, sa, off);
        sc += __shfl_xor_sync(0xFFFFFFFFu, sc, off);
    }
    if (lane == 0) { g_a[warp] = sa; g_c[warp] = sc; }
}

// ---------------------------------------------------------------------------
// helpers
// ---------------------------------------------------------------------------
__device__ __forceinline__ void fma2(unsigned long long& a,
                                     unsigned long long xv,
                                     unsigned long long pp) {
    asm("fma.rn.f32x2 %0, %1, %2, %0;" : "+l"(a) : "l"(xv), "l"(pp));
}
__device__ __forceinline__ float2 u2f(unsigned long long v) {
    float2 r;
    asm("mov.b64 {%0,%1}, %2;" : "=f"(r.x), "=f"(r.y) : "l"(v));
    return r;
}
__device__ __forceinline__ void cp16(void* s, const void* g) {
    unsigned sa = (unsigned)__cvta_generic_to_shared(s);
    asm volatile("cp.async.cg.shared.global [%0], [%1], 16;" :: "r"(sa), "l"(g));
}
__device__ __forceinline__ void cp_commit() {
    asm volatile("cp.async.commit_group;");
}
template <int N>
__device__ __forceinline__ void cp_wait() {
    asm volatile("cp.async.wait_group %0;" :: "n"(N));
}

// ---------------------------------------------------------------------------
// Kernel B (fused softmax + windowed sum + x-copy).
// 128 threads: d4 = tid&31 (float4 column), tg = tid>>5 (8 t's per thread).
// pd stored pre-duplicated {p,p} (16KB) -> zero repack movs in the hot loop.
// smem ~49.5KB -> 4 CTAs/SM.
// ---------------------------------------------------------------------------
__global__ void __launch_bounds__(128, 4)
k_attn(const float* __restrict__ x, const float* __restrict__ bb,
       float* __restrict__ out) {
    extern __shared__ float smem[];
    float*  xs = smem;                                       // 64*128 f = 32KB
    float2* pd = reinterpret_cast<float2*>(smem + HR * DC);  // 64*32 f2 = 16KB
    float*  sc_a = reinterpret_cast<float*>(pd + HR * TT);   // 32 f
    float*  sc_c = sc_a + TT;                                // 64 f

    const int tid = threadIdx.x;
    const int d0 = blockIdx.x * DC;
    const int t0 = blockIdx.y * TT;
    const int b  = blockIdx.z;

    // ---- issue 4 cp.async stages (16 rows x 32 f4 each = 512 f4/stage) ----
    const float4* x4 = reinterpret_cast<const float4*>(x);
    float4* xs4 = reinterpret_cast<float4*>(xs);
#pragma unroll
    for (int s = 0; s < 4; s++) {
#pragma unroll
        for (int k = 0; k < 4; k++) {
            int idx = s * 512 + k * 128 + tid;
            int row = idx >> 5;
            int col = idx & 31;
            int gr = t0 - WIN + row;
            gr = gr < 0 ? 0 : (gr > T_DIM - 1 ? T_DIM - 1 : gr);
            cp16(&xs4[idx], &x4[((size_t)gr * B_DIM + b) * (D_DIM / 4) + (d0 >> 2) + col]);
        }
        cp_commit();
    }

    // ---- preload a/c windows + zero pd while loads fly ----
    if (tid < TT) sc_a[tid] = g_a[(t0 + tid) * B_DIM + b];
    else if (tid < TT + HR) {
        int i = tid - TT;
        int gr = t0 - WIN + i;
        sc_c[i] = (gr >= 0 && gr < T_DIM) ? g_c[gr * B_DIM + b] : -INFINITY;
    }
#pragma unroll
    for (int i = tid; i < HR * TT; i += 128) pd[i] = make_float2(0.f, 0.f);
    __syncthreads();

    // ---- warp 0: softmax for 32 t's, scatter {p,p} diagonally into pd ----
    if (tid < 32) {
        const int tl = tid;
        const float base = sc_a[tl] + bb[0];
        float sv[WSZ];
        float m = -INFINITY;
#pragma unroll
        for (int wi = 0; wi < WSZ; wi++) {
            float v = base + sc_c[tl + wi];
            sv[wi] = v;
            m = fmaxf(m, v);
        }
        float sum = 0.f;
#pragma unroll
        for (int wi = 0; wi < WSZ; wi++) {
            float e = (sv[wi] == -INFINITY) ? 0.f : __expf(sv[wi] - m);
            sv[wi] = e;
            sum += e;
        }
        float inv = 1.f / sum;
#pragma unroll
        for (int wi = 0; wi < WSZ; wi++) {
            float p = sv[wi] * inv;
            pd[(tl + wi) * TT + tl] = make_float2(p, p);
        }
    }

    const int d4 = tid & 31;    // float4 column
    const int tg = tid >> 5;    // warp id = t-group (8 t's)
    const int tb = tg * 8;

    unsigned long long acc[16];
#pragma unroll
    for (int j = 0; j < 16; j++) acc[j] = 0ULL;

    const ulonglong2* xsq = reinterpret_cast<const ulonglong2*>(xs);
    const ulonglong2* pdq = reinterpret_cast<const ulonglong2*>(pd);
    float4* o4 = reinterpret_cast<float4*>(out);
    const size_t ocopy = ((size_t)(t0 + tb) * B_DIM + b) * 512 + (d0 >> 2) + d4;

#define ROW_STEP(r, DO_COPY)                                              \
    {                                                                     \
        int row = tb + (r);                                               \
        ulonglong2 xv = xsq[row * 32 + d4];                               \
        int pbase = row * 16 + tg * 4;   /* pd[row][tb..tb+7] as 4 ull2 */\
        ulonglong2 q0 = pdq[pbase + 0];                                   \
        ulonglong2 q1 = pdq[pbase + 1];                                   \
        ulonglong2 q2 = pdq[pbase + 2];                                   \
        ulonglong2 q3 = pdq[pbase + 3];                                   \
        fma2(acc[0],  xv.x, q0.x); fma2(acc[1],  xv.y, q0.x);             \
        fma2(acc[2],  xv.x, q0.y); fma2(acc[3],  xv.y, q0.y);             \
        fma2(acc[4],  xv.x, q1.x); fma2(acc[5],  xv.y, q1.x);             \
        fma2(acc[6],  xv.x, q1.y); fma2(acc[7],  xv.y, q1.y);             \
        fma2(acc[8],  xv.x, q2.x); fma2(acc[9],  xv.y, q2.x);             \
        fma2(acc[10], xv.x, q2.y); fma2(acc[11], xv.y, q2.y);             \
        fma2(acc[12], xv.x, q3.x); fma2(acc[13], xv.y, q3.x);             \
        fma2(acc[14], xv.x, q3.y); fma2(acc[15], xv.y, q3.y);             \
        if (DO_COPY) {                                                    \
            float2 lo = u2f(xv.x), hi = u2f(xv.y);                        \
            __stcs(&o4[ocopy + (size_t)((r) - 16) * B_DIM * 512],         \
                   make_float4(lo.x, lo.y, hi.x, hi.y));                  \
        }                                                                 \
    }

    // step r touches row tb+r (tb <= 24). Stage s covers rows [16s,16s+15].
    cp_wait<2>();            // rows 0..31 ready
    __syncthreads();         // + pd visible
#pragma unroll
    for (int r = 0; r < 8; r++) ROW_STEP(r, false);   // max row 31

    cp_wait<1>();            // rows 0..47 ready
    __syncthreads();
#pragma unroll
    for (int r = 8; r < 16; r++) ROW_STEP(r, false);  // max row 39
#pragma unroll
    for (int r = 16; r < 24; r++) ROW_STEP(r, true);  // copy rows, max row 47

    cp_wait<0>();            // all rows
    __syncthreads();
#pragma unroll
    for (int r = 24; r < 40; r++) ROW_STEP(r, false); // max row 63
#undef ROW_STEP

    // attn half: out[t, b, D + d]
#pragma unroll
    for (int j = 0; j < 8; j++) {
        int t = t0 + tb + j;
        float2 lo = u2f(acc[2 * j]);
        float2 hi = u2f(acc[2 * j + 1]);
        __stcs(&o4[((size_t)t * B_DIM + b) * 512 + (D_DIM / 4) + (d0 >> 2) + d4],
               make_float4(lo.x, lo.y, hi.x, hi.y));
    }
}

// ---------------------------------------------------------------------------
extern "C" void kernel_launch(void* const* d_in, const int* in_sizes, int n_in,
                              void* d_out, int out_size) {
    const float* x  = reinterpret_cast<const float*>(d_in[0]);
    const float* w  = reinterpret_cast<const float*>(d_in[1]);
    const float* bb = reinterpret_cast<const float*>(d_in[2]);
    float* out = reinterpret_cast<float*>(d_out);

    const int smem_bytes = HR * DC * 4 + HR * TT * 8 + (TT + HR) * 4 + 16;
    cudaFuncSetAttribute(k_attn, cudaFuncAttributeMaxDynamicSharedMemorySize, smem_bytes);

    k_dots<<<(T_DIM * B_DIM) / 8, 256>>>(x, w);
    dim3 grid(D_DIM / DC, T_DIM / TT, B_DIM);
    k_attn<<<grid, 128, smem_bytes>>>(x, bb, out);
}